// round 1
// baseline (speedup 1.0000x reference)
#include <cuda_runtime.h>
#include <cuda_bf16.h>
#include <stdint.h>

#define N_NODES 10000
#define N_EDGES 160000
#define IN_C 256
#define HID_C 512
#define OUT_C 256

// ---------------- device scratch (no allocations allowed) ----------------
__device__ float g_xw1[N_NODES * HID_C];   // X @ W1
__device__ float g_h1 [N_NODES * HID_C];   // layer-1 output (post relu/dropout)
__device__ float g_xw2[N_NODES * OUT_C];   // H1 @ W2
__device__ float g_dinv[N_NODES];
__device__ int   g_cnt[N_NODES];
__device__ int   g_off[N_NODES + 1];
__device__ int   g_cur[N_NODES];
__device__ int   g_csr[N_EDGES];
__device__ int   g_is64;

// ---------------- threefry2x32 (JAX-compatible) ----------------
#define TF_ROUND(v0, v1, r) do { (v0) += (v1); (v1) = ((v1) << (r)) | ((v1) >> (32 - (r))); (v1) ^= (v0); } while (0)

__host__ __device__ inline void tf2x32(unsigned k0, unsigned k1,
                                       unsigned x0, unsigned x1,
                                       unsigned& o0, unsigned& o1) {
    unsigned ks0 = k0, ks1 = k1, ks2 = k0 ^ k1 ^ 0x1BD11BDAu;
    unsigned v0 = x0 + ks0, v1 = x1 + ks1;
    TF_ROUND(v0, v1, 13); TF_ROUND(v0, v1, 15); TF_ROUND(v0, v1, 26); TF_ROUND(v0, v1, 6);
    v0 += ks1; v1 += ks2 + 1u;
    TF_ROUND(v0, v1, 17); TF_ROUND(v0, v1, 29); TF_ROUND(v0, v1, 16); TF_ROUND(v0, v1, 24);
    v0 += ks2; v1 += ks0 + 2u;
    TF_ROUND(v0, v1, 13); TF_ROUND(v0, v1, 15); TF_ROUND(v0, v1, 26); TF_ROUND(v0, v1, 6);
    v0 += ks0; v1 += ks1 + 3u;
    TF_ROUND(v0, v1, 17); TF_ROUND(v0, v1, 29); TF_ROUND(v0, v1, 16); TF_ROUND(v0, v1, 24);
    v0 += ks1; v1 += ks2 + 4u;
    TF_ROUND(v0, v1, 13); TF_ROUND(v0, v1, 15); TF_ROUND(v0, v1, 26); TF_ROUND(v0, v1, 6);
    v0 += ks2; v1 += ks0 + 5u;
    o0 = v0; o1 = v1;
}

// ---------------- edge dtype detection (int32 vs int64) ----------------
__global__ void detect_kernel(const int* __restrict__ ei32) {
    __shared__ int orv;
    if (threadIdx.x == 0) orv = 0;
    __syncthreads();
    // If data is int64 (indices < 2^31), all odd 32-bit words are 0.
    // If int32, odd words are random indices in [0, 10000) -> virtually surely nonzero.
    int v = ei32[threadIdx.x * 2 + 1];
    if (v != 0) atomicOr(&orv, 1);
    __syncthreads();
    if (threadIdx.x == 0) g_is64 = (orv == 0) ? 1 : 0;
}

__device__ inline int edge_at(const void* ei, int pos) {
    if (g_is64) return (int)((const long long*)ei)[pos];
    return ((const int*)ei)[pos];
}

// ---------------- graph preprocessing ----------------
__global__ void zero_cnt_kernel() {
    int i = blockIdx.x * blockDim.x + threadIdx.x;
    if (i < N_NODES) g_cnt[i] = 0;
}

__global__ void count_kernel(const void* __restrict__ ei) {
    int e = blockIdx.x * blockDim.x + threadIdx.x;
    if (e >= N_EDGES) return;
    int d = edge_at(ei, N_EDGES + e);  // dst row
    atomicAdd(&g_cnt[d], 1);
}

__global__ void dinv_kernel() {
    int i = blockIdx.x * blockDim.x + threadIdx.x;
    if (i < N_NODES) g_dinv[i] = 1.0f / sqrtf((float)(g_cnt[i] + 1));  // +1 self loop
}

__global__ void scan_kernel() {
    __shared__ int sh[1024];
    int carry = 0;
    for (int base = 0; base < N_NODES; base += 1024) {
        int i = base + (int)threadIdx.x;
        int v = (i < N_NODES) ? g_cnt[i] : 0;
        sh[threadIdx.x] = v;
        __syncthreads();
        for (int off = 1; off < 1024; off <<= 1) {
            int t = (threadIdx.x >= (unsigned)off) ? sh[threadIdx.x - off] : 0;
            __syncthreads();
            sh[threadIdx.x] += t;
            __syncthreads();
        }
        if (i < N_NODES) {
            int excl = sh[threadIdx.x] - v + carry;
            g_off[i] = excl;
            g_cur[i] = excl;
        }
        carry += sh[1023];
        __syncthreads();
    }
    if (threadIdx.x == 0) g_off[N_NODES] = carry;
}

__global__ void fill_kernel(const void* __restrict__ ei) {
    int e = blockIdx.x * blockDim.x + threadIdx.x;
    if (e >= N_EDGES) return;
    int s = edge_at(ei, e);
    int d = edge_at(ei, N_EDGES + e);
    int pos = atomicAdd(&g_cur[d], 1);
    g_csr[pos] = s;
}

// ---------------- tiled fp32 GEMM: C[M,N] = A[M,K] @ B[K,N] ----------------
// BM=128, BN=64, BK=16, 256 threads, 8x4 micro-tile per thread.
__global__ void __launch_bounds__(256) gemm_kernel(
    const float* __restrict__ A, const float* __restrict__ B,
    float* __restrict__ C, int M, int N, int K)
{
    __shared__ float As[16][128];
    __shared__ float Bs[16][64];
    const int tid = threadIdx.x;
    const int bm = blockIdx.y * 128;
    const int bn = blockIdx.x * 64;
    const int trow = (tid >> 4) * 8;   // 0..120
    const int tcol = (tid & 15) * 4;   // 0..60

    float acc[8][4];
#pragma unroll
    for (int i = 0; i < 8; i++)
#pragma unroll
        for (int j = 0; j < 4; j++) acc[i][j] = 0.0f;

    for (int k0 = 0; k0 < K; k0 += 16) {
        // A tile 128x16 -> transposed into As[k][m]
#pragma unroll
        for (int rep = 0; rep < 2; rep++) {
            int lin = tid + rep * 256;        // 0..511
            int row = lin >> 2;               // 0..127
            int c4  = (lin & 3) * 4;          // 0,4,8,12
            float4 v = make_float4(0.f, 0.f, 0.f, 0.f);
            int gr = bm + row;
            if (gr < M) v = *(const float4*)(A + (size_t)gr * K + k0 + c4);
            As[c4 + 0][row] = v.x;
            As[c4 + 1][row] = v.y;
            As[c4 + 2][row] = v.z;
            As[c4 + 3][row] = v.w;
        }
        // B tile 16x64
        {
            int row = tid >> 4;               // 0..15
            int c4  = (tid & 15) * 4;
            float4 v = *(const float4*)(B + (size_t)(k0 + row) * N + bn + c4);
            *(float4*)&Bs[row][c4] = v;
        }
        __syncthreads();
#pragma unroll
        for (int k = 0; k < 16; k++) {
            float ra[8], rb[4];
#pragma unroll
            for (int i = 0; i < 8; i++) ra[i] = As[k][trow + i];
#pragma unroll
            for (int j = 0; j < 4; j++) rb[j] = Bs[k][tcol + j];
#pragma unroll
            for (int i = 0; i < 8; i++)
#pragma unroll
                for (int j = 0; j < 4; j++)
                    acc[i][j] = fmaf(ra[i], rb[j], acc[i][j]);
        }
        __syncthreads();
    }
#pragma unroll
    for (int i = 0; i < 8; i++) {
        int gr = bm + trow + i;
        if (gr < M) {
            float4 v = make_float4(acc[i][0], acc[i][1], acc[i][2], acc[i][3]);
            *(float4*)(C + (size_t)gr * N + bn + tcol) = v;
        }
    }
}

// ---------------- gather-based GCN aggregation + bias + relu ----------------
// grid.x = node, blockDim.x = C (512 or 256). out[n,c] = relu( dinv[n]*(dinv[n]*xw[n,c]
//   + sum_{s in in(n)} dinv[s]*xw[s,c]) + b[c] )
__global__ void aggregate_kernel(const float* __restrict__ xw,
                                 const float* __restrict__ bias,
                                 float* __restrict__ out, int C)
{
    int n = blockIdx.x;
    int c = threadIdx.x;
    float dn = g_dinv[n];
    float acc = dn * xw[(size_t)n * C + c];
    int k0 = g_off[n], k1 = g_off[n + 1];
    for (int k = k0; k < k1; k++) {
        int s = g_csr[k];
        acc += g_dinv[s] * xw[(size_t)s * C + c];
    }
    float v = acc * dn + bias[c];
    out[(size_t)n * C + c] = fmaxf(v, 0.0f);
}

// ---------------- dropout (JAX partitionable threefry, p=0.5) ----------------
__global__ void dropout_kernel(float* __restrict__ x, int n, unsigned k0, unsigned k1) {
    int i = blockIdx.x * blockDim.x + threadIdx.x;
    if (i >= n) return;
    unsigned y0, y1;
    tf2x32(k0, k1, 0u, (unsigned)i, y0, y1);   // 64-bit counter = i (hi=0, lo=i)
    unsigned bits = y0 ^ y1;                   // partitionable 32-bit combine
    float u = __uint_as_float((bits >> 9) | 0x3f800000u) - 1.0f;
    x[i] = (u < 0.5f) ? x[i] * 2.0f : 0.0f;
}

// ---------------- launch ----------------
extern "C" void kernel_launch(void* const* d_in, const int* in_sizes, int n_in,
                              void* d_out, int out_size)
{
    const float* x  = (const float*)d_in[0];
    const void*  ei = d_in[1];
    const float* W1 = (const float*)d_in[2];
    const float* b1 = (const float*)d_in[3];
    const float* W2 = (const float*)d_in[4];
    const float* b2 = (const float*)d_in[5];
    float* out = (float*)d_out;

    float *p_xw1, *p_h1, *p_xw2;
    cudaGetSymbolAddress((void**)&p_xw1, g_xw1);
    cudaGetSymbolAddress((void**)&p_h1,  g_h1);
    cudaGetSymbolAddress((void**)&p_xw2, g_xw2);

    // Derive dropout keys on host: split(key(42)) with partitionable fold-like split.
    unsigned dk1_0, dk1_1, dk2_0, dk2_1;
    tf2x32(0u, 42u, 0u, 0u, dk1_0, dk1_1);
    tf2x32(0u, 42u, 0u, 1u, dk2_0, dk2_1);

    // Graph preprocessing
    detect_kernel<<<1, 1024>>>((const int*)ei);
    zero_cnt_kernel<<<(N_NODES + 255) / 256, 256>>>();
    count_kernel<<<(N_EDGES + 255) / 256, 256>>>(ei);
    dinv_kernel<<<(N_NODES + 255) / 256, 256>>>();
    scan_kernel<<<1, 1024>>>();
    fill_kernel<<<(N_EDGES + 255) / 256, 256>>>(ei);

    // Layer 1: XW1 -> aggregate (+b1, relu) -> dropout(dk1)
    {
        dim3 grid(HID_C / 64, (N_NODES + 127) / 128);
        gemm_kernel<<<grid, 256>>>(x, W1, p_xw1, N_NODES, HID_C, IN_C);
    }
    aggregate_kernel<<<N_NODES, HID_C>>>(p_xw1, b1, p_h1, HID_C);
    {
        int n = N_NODES * HID_C;
        dropout_kernel<<<(n + 255) / 256, 256>>>(p_h1, n, dk1_0, dk1_1);
    }

    // Layer 2: H1@W2 -> aggregate (+b2, relu) into d_out -> dropout(dk2)
    {
        dim3 grid(OUT_C / 64, (N_NODES + 127) / 128);
        gemm_kernel<<<grid, 256>>>(p_h1, W2, p_xw2, N_NODES, OUT_C, HID_C);
    }
    aggregate_kernel<<<N_NODES, OUT_C>>>(p_xw2, b2, out, OUT_C);
    {
        int n = N_NODES * OUT_C;
        dropout_kernel<<<(n + 255) / 256, 256>>>(out, n, dk2_0, dk2_1);
    }
}

// round 3
// speedup vs baseline: 1.5396x; 1.5396x over previous
#include <cuda_runtime.h>
#include <stdint.h>

#define N_NODES 10000
#define N_EDGES 160000
#define IN_C 256
#define HID_C 512
#define OUT_C 256

// ---------------- device scratch (no allocations allowed) ----------------
__device__ float g_xw1[N_NODES * HID_C];
__device__ float g_h1 [N_NODES * HID_C];
__device__ float g_xw2[N_NODES * OUT_C];
__device__ float g_w1t[HID_C * IN_C];    // W1^T [512,256] K-major
__device__ float g_w2t[OUT_C * HID_C];   // W2^T [256,512] K-major
__device__ float g_dinv[N_NODES];
__device__ int   g_cnt[N_NODES];
__device__ int   g_off[N_NODES + 1];
__device__ int   g_cur[N_NODES];
__device__ int   g_csr[N_EDGES];
__device__ int   g_is64;

// ---------------- small PTX helpers (all sm_80-portable) ----------------
__device__ __forceinline__ uint32_t smem_to_u32(const void* p) {
    uint32_t a;
    asm("{ .reg .u64 t; cvta.to.shared.u64 t, %1; cvt.u32.u64 %0, t; }" : "=r"(a) : "l"(p));
    return a;
}
__device__ __forceinline__ uint32_t f2tf32(float f) {
    uint32_t r;
    asm("cvt.rna.tf32.f32 %0, %1;" : "=r"(r) : "f"(f));
    return r;
}
__device__ __forceinline__ void cp_async16(uint32_t dst, const void* src) {
    asm volatile("cp.async.cg.shared.global [%0], [%1], 16;" :: "r"(dst), "l"(src));
}
#define CP_COMMIT()  asm volatile("cp.async.commit_group;" ::: "memory")
#define CP_WAIT(n)   asm volatile("cp.async.wait_group %0;" :: "n"(n) : "memory")

// m16n8k8 tf32 MMA, row.col, fp32 accumulate
__device__ __forceinline__ void mma_tf32(float* d, const uint32_t* a, const uint32_t* b) {
    asm volatile(
        "mma.sync.aligned.m16n8k8.row.col.f32.tf32.tf32.f32 "
        "{%0,%1,%2,%3},{%4,%5,%6,%7},{%8,%9},{%0,%1,%2,%3};"
        : "+f"(d[0]), "+f"(d[1]), "+f"(d[2]), "+f"(d[3])
        : "r"(a[0]), "r"(a[1]), "r"(a[2]), "r"(a[3]), "r"(b[0]), "r"(b[1]));
}

// ---------------- threefry2x32 (JAX-compatible) ----------------
#define TF_ROUND(v0, v1, r) do { (v0) += (v1); (v1) = ((v1) << (r)) | ((v1) >> (32 - (r))); (v1) ^= (v0); } while (0)
__host__ __device__ inline void tf2x32(unsigned k0, unsigned k1,
                                       unsigned x0, unsigned x1,
                                       unsigned& o0, unsigned& o1) {
    unsigned ks0 = k0, ks1 = k1, ks2 = k0 ^ k1 ^ 0x1BD11BDAu;
    unsigned v0 = x0 + ks0, v1 = x1 + ks1;
    TF_ROUND(v0, v1, 13); TF_ROUND(v0, v1, 15); TF_ROUND(v0, v1, 26); TF_ROUND(v0, v1, 6);
    v0 += ks1; v1 += ks2 + 1u;
    TF_ROUND(v0, v1, 17); TF_ROUND(v0, v1, 29); TF_ROUND(v0, v1, 16); TF_ROUND(v0, v1, 24);
    v0 += ks2; v1 += ks0 + 2u;
    TF_ROUND(v0, v1, 13); TF_ROUND(v0, v1, 15); TF_ROUND(v0, v1, 26); TF_ROUND(v0, v1, 6);
    v0 += ks0; v1 += ks1 + 3u;
    TF_ROUND(v0, v1, 17); TF_ROUND(v0, v1, 29); TF_ROUND(v0, v1, 16); TF_ROUND(v0, v1, 24);
    v0 += ks1; v1 += ks2 + 4u;
    TF_ROUND(v0, v1, 13); TF_ROUND(v0, v1, 15); TF_ROUND(v0, v1, 26); TF_ROUND(v0, v1, 6);
    v0 += ks2; v1 += ks0 + 5u;
    o0 = v0; o1 = v1;
}

// ---------------- edge dtype detection (int32 vs int64) ----------------
__global__ void detect_kernel(const int* __restrict__ ei32) {
    __shared__ int orv;
    if (threadIdx.x == 0) orv = 0;
    __syncthreads();
    int v = ei32[threadIdx.x * 2 + 1];
    if (v != 0) atomicOr(&orv, 1);
    __syncthreads();
    if (threadIdx.x == 0) g_is64 = (orv == 0) ? 1 : 0;
}
__device__ inline int edge_at(const void* ei, int pos) {
    if (g_is64) return (int)((const long long*)ei)[pos];
    return ((const int*)ei)[pos];
}

// ---------------- graph preprocessing ----------------
__global__ void zero_cnt_kernel() {
    int i = blockIdx.x * blockDim.x + threadIdx.x;
    if (i < N_NODES) g_cnt[i] = 0;
}
__global__ void count_kernel(const void* __restrict__ ei) {
    int e = blockIdx.x * blockDim.x + threadIdx.x;
    if (e >= N_EDGES) return;
    atomicAdd(&g_cnt[edge_at(ei, N_EDGES + e)], 1);
}
__global__ void dinv_kernel() {
    int i = blockIdx.x * blockDim.x + threadIdx.x;
    if (i < N_NODES) g_dinv[i] = 1.0f / sqrtf((float)(g_cnt[i] + 1));
}
__global__ void scan_kernel() {
    __shared__ int sh[1024];
    int carry = 0;
    for (int base = 0; base < N_NODES; base += 1024) {
        int i = base + (int)threadIdx.x;
        int v = (i < N_NODES) ? g_cnt[i] : 0;
        sh[threadIdx.x] = v;
        __syncthreads();
        for (int off = 1; off < 1024; off <<= 1) {
            int t = (threadIdx.x >= (unsigned)off) ? sh[threadIdx.x - off] : 0;
            __syncthreads();
            sh[threadIdx.x] += t;
            __syncthreads();
        }
        if (i < N_NODES) {
            int excl = sh[threadIdx.x] - v + carry;
            g_off[i] = excl;
            g_cur[i] = excl;
        }
        carry += sh[1023];
        __syncthreads();
    }
    if (threadIdx.x == 0) g_off[N_NODES] = carry;
}
__global__ void fill_kernel(const void* __restrict__ ei) {
    int e = blockIdx.x * blockDim.x + threadIdx.x;
    if (e >= N_EDGES) return;
    int s = edge_at(ei, e);
    int d = edge_at(ei, N_EDGES + e);
    g_csr[atomicAdd(&g_cur[d], 1)] = s;
}

// ---------------- weight transpose (to K-major B operand) ----------------
__global__ void transpose_kernel(const float* __restrict__ in, float* __restrict__ out,
                                 int R, int C) {  // in [R,C] -> out [C,R]
    __shared__ float tile[32][33];
    int c0 = blockIdx.x * 32, r0 = blockIdx.y * 32;
#pragma unroll
    for (int i = 0; i < 32; i += 8) {
        int r = r0 + threadIdx.y + i, c = c0 + threadIdx.x;
        if (r < R && c < C) tile[threadIdx.y + i][threadIdx.x] = in[(size_t)r * C + c];
    }
    __syncthreads();
#pragma unroll
    for (int i = 0; i < 32; i += 8) {
        int c = c0 + threadIdx.y + i, r = r0 + threadIdx.x;
        if (r < R && c < C) out[(size_t)c * R + r] = tile[threadIdx.x][threadIdx.y + i];
    }
}

// ---------------- tensor-core tf32 GEMM: C[M,N_OUT] = A[M,K] @ Bt^T ----------------
// A [M,K] row-major, Bt [N_OUT,K] row-major (i.e., B col-major). BM=128, BN=128, BK=32.
// 8 warps in 4(m) x 2(n); warp tile 32x64 = 2(m) x 8(n) m16n8k8 atoms.
// smem rows padded to 36 floats -> fragment LDS bank-conflict-free.
#define SROW 36
#define S_BUF (256 * SROW)   // floats per buffer (128 A rows + 128 B rows)

template <int N_OUT, int K_TOT>
__global__ void __launch_bounds__(256)
mma_gemm_kernel(const float* __restrict__ A, const float* __restrict__ Bt,
                float* __restrict__ C, int M)
{
    extern __shared__ float sm[];
    const int tid = threadIdx.x;
    const int wid = tid >> 5, lane = tid & 31;
    const int g = lane >> 2, tig = lane & 3;
    const int wm = wid >> 1, wn = wid & 1;
    const int bm = blockIdx.y * 128;
    const int bn = blockIdx.x * 128;
    constexpr int NBK = K_TOT / 32;

    const uint32_t sbase = smem_to_u32(sm);

    float acc[2][8][4];
#pragma unroll
    for (int mi = 0; mi < 2; mi++)
#pragma unroll
        for (int ni = 0; ni < 8; ni++)
#pragma unroll
            for (int j = 0; j < 4; j++) acc[mi][ni][j] = 0.0f;

    // tile loader: 4 A-chunks + 4 B-chunks of 16B per thread
    auto load_tile = [&](int kc, int buf) {
#pragma unroll
        for (int r = 0; r < 4; r++) {
            int chunk = r * 256 + tid;          // 0..1023
            int row = chunk >> 3;               // 0..127
            int f4  = chunk & 7;                // 0..7
            int gr = bm + row; if (gr >= M) gr = M - 1;
            uint32_t dA = sbase + (uint32_t)(buf * S_BUF + row * SROW + f4 * 4) * 4u;
            cp_async16(dA, A + (size_t)gr * K_TOT + kc * 32 + f4 * 4);
            int gn = bn + row;
            uint32_t dB = sbase + (uint32_t)(buf * S_BUF + (128 + row) * SROW + f4 * 4) * 4u;
            cp_async16(dB, Bt + (size_t)gn * K_TOT + kc * 32 + f4 * 4);
        }
    };

    load_tile(0, 0);
    CP_COMMIT();

    for (int kc = 0; kc < NBK; kc++) {
        int buf = kc & 1;
        if (kc + 1 < NBK) {
            load_tile(kc + 1, buf ^ 1);
            CP_COMMIT();
            CP_WAIT(1);
        } else {
            CP_WAIT(0);
        }
        __syncthreads();

        const float* As = sm + buf * S_BUF;
        const float* Bs = As + 128 * SROW;
        const int rm = wm * 32;
        const int cn = wn * 64;

#pragma unroll
        for (int s = 0; s < 4; s++) {
            int k0 = s * 8;
            uint32_t af[2][4];
#pragma unroll
            for (int mi = 0; mi < 2; mi++) {
                int r0 = rm + mi * 16 + g;
                af[mi][0] = f2tf32(As[r0 * SROW + k0 + tig]);
                af[mi][1] = f2tf32(As[(r0 + 8) * SROW + k0 + tig]);
                af[mi][2] = f2tf32(As[r0 * SROW + k0 + tig + 4]);
                af[mi][3] = f2tf32(As[(r0 + 8) * SROW + k0 + tig + 4]);
            }
#pragma unroll
            for (int ni = 0; ni < 8; ni++) {
                int n0 = cn + ni * 8 + g;
                uint32_t bf[2];
                bf[0] = f2tf32(Bs[n0 * SROW + k0 + tig]);
                bf[1] = f2tf32(Bs[n0 * SROW + k0 + tig + 4]);
                mma_tf32(acc[0][ni], af[0], bf);
                mma_tf32(acc[1][ni], af[1], bf);
            }
        }
        __syncthreads();
    }

    // epilogue
#pragma unroll
    for (int mi = 0; mi < 2; mi++) {
        int m0 = bm + wm * 32 + mi * 16 + g;
        int m1 = m0 + 8;
#pragma unroll
        for (int ni = 0; ni < 8; ni++) {
            int n0 = bn + wn * 64 + ni * 8 + tig * 2;
            if (m0 < M) {
                float2 v0 = make_float2(acc[mi][ni][0], acc[mi][ni][1]);
                *(float2*)(C + (size_t)m0 * N_OUT + n0) = v0;
            }
            if (m1 < M) {
                float2 v1 = make_float2(acc[mi][ni][2], acc[mi][ni][3]);
                *(float2*)(C + (size_t)m1 * N_OUT + n0) = v1;
            }
        }
    }
}

// ---------------- aggregation + bias + relu + fused dropout ----------------
__global__ void aggregate_kernel(const float* __restrict__ xw,
                                 const float* __restrict__ bias,
                                 float* __restrict__ out, int C,
                                 unsigned dk0, unsigned dk1)
{
    int n = blockIdx.x;
    int c = threadIdx.x;
    float dn = g_dinv[n];
    float acc = dn * xw[(size_t)n * C + c];
    int k0 = g_off[n], k1 = g_off[n + 1];
    for (int k = k0; k < k1; k++) {
        int s = g_csr[k];
        acc += g_dinv[s] * xw[(size_t)s * C + c];
    }
    float v = fmaxf(acc * dn + bias[c], 0.0f);
    // fused dropout (JAX partitionable threefry, p=0.5)
    unsigned i = (unsigned)(n * C + c);
    unsigned y0, y1;
    tf2x32(dk0, dk1, 0u, i, y0, y1);
    unsigned bits = y0 ^ y1;
    float u = __uint_as_float((bits >> 9) | 0x3f800000u) - 1.0f;
    out[(size_t)n * C + c] = (u < 0.5f) ? v * 2.0f : 0.0f;
}

// ---------------- launch ----------------
extern "C" void kernel_launch(void* const* d_in, const int* in_sizes, int n_in,
                              void* d_out, int out_size)
{
    const float* x  = (const float*)d_in[0];
    const void*  ei = d_in[1];
    const float* W1 = (const float*)d_in[2];
    const float* b1 = (const float*)d_in[3];
    const float* W2 = (const float*)d_in[4];
    const float* b2 = (const float*)d_in[5];
    float* out = (float*)d_out;

    float *p_xw1, *p_h1, *p_xw2, *p_w1t, *p_w2t;
    cudaGetSymbolAddress((void**)&p_xw1, g_xw1);
    cudaGetSymbolAddress((void**)&p_h1,  g_h1);
    cudaGetSymbolAddress((void**)&p_xw2, g_xw2);
    cudaGetSymbolAddress((void**)&p_w1t, g_w1t);
    cudaGetSymbolAddress((void**)&p_w2t, g_w2t);

    constexpr int SMEM_BYTES = 2 * S_BUF * 4;  // 73,728 B
    cudaFuncSetAttribute(mma_gemm_kernel<HID_C, IN_C>,
                         cudaFuncAttributeMaxDynamicSharedMemorySize, SMEM_BYTES);
    cudaFuncSetAttribute(mma_gemm_kernel<OUT_C, HID_C>,
                         cudaFuncAttributeMaxDynamicSharedMemorySize, SMEM_BYTES);

    // dropout keys: split(key(42)), partitionable
    unsigned dk1_0, dk1_1, dk2_0, dk2_1;
    tf2x32(0u, 42u, 0u, 0u, dk1_0, dk1_1);
    tf2x32(0u, 42u, 0u, 1u, dk2_0, dk2_1);

    // graph preprocessing + weight transposes
    detect_kernel<<<1, 1024>>>((const int*)ei);
    zero_cnt_kernel<<<(N_NODES + 255) / 256, 256>>>();
    count_kernel<<<(N_EDGES + 255) / 256, 256>>>(ei);
    dinv_kernel<<<(N_NODES + 255) / 256, 256>>>();
    scan_kernel<<<1, 1024>>>();
    fill_kernel<<<(N_EDGES + 255) / 256, 256>>>(ei);
    {
        dim3 blk(32, 8);
        transpose_kernel<<<dim3(HID_C / 32, IN_C / 32), blk>>>(W1, p_w1t, IN_C, HID_C);
        transpose_kernel<<<dim3(OUT_C / 32, HID_C / 32), blk>>>(W2, p_w2t, HID_C, OUT_C);
    }

    const int grid_m = (N_NODES + 127) / 128;  // 79

    // Layer 1: X @ W1 (M=10000, N=512, K=256)
    mma_gemm_kernel<HID_C, IN_C><<<dim3(HID_C / 128, grid_m), 256, SMEM_BYTES>>>(
        x, p_w1t, p_xw1, N_NODES);
    aggregate_kernel<<<N_NODES, HID_C>>>(p_xw1, b1, p_h1, HID_C, dk1_0, dk1_1);

    // Layer 2: H1 @ W2 (M=10000, N=256, K=512)
    mma_gemm_kernel<OUT_C, HID_C><<<dim3(OUT_C / 128, grid_m), 256, SMEM_BYTES>>>(
        p_h1, p_w2t, p_xw2, N_NODES);
    aggregate_kernel<<<N_NODES, OUT_C>>>(p_xw2, b2, out, OUT_C, dk2_0, dk2_1);
}